// round 2
// baseline (speedup 1.0000x reference)
#include <cuda_runtime.h>
#include <cuda_fp16.h>
#include <cstdint>

// ============================================================
// DST-II as GEMM: y[16384,1024] = x[16384,1024] @ S[1024,1024]
// S[n][k] = sin(pi/1024 * (n+0.5) * (k+1))
// Single-pass fp16 mma.sync (f32 accum). Base ISA only
// (cp.async + ldmatrix + mma.sync) — no sm_103a-only features.
// ============================================================

#define BATCH   16384
#define NDIM    1024
#define TILE_M  128
#define TILE_N  128
#define KB      64            // K per chunk (64 fp16 = 128B rows)
#define NCHUNK  (NDIM / KB)   // 16
#define NSTAGE  4
#define STAGE_A 16384         // 128 rows * 128B
#define STAGE_B 16384
#define STAGE_BYTES (STAGE_A + STAGE_B)
#define SMEM_TOTAL  (NSTAGE * STAGE_BYTES)   // 131072

// ---------------- device scratch ----------------
__device__ __half g_x[(size_t)BATCH * NDIM];   // x in fp16
__device__ __half g_S[(size_t)NDIM * NDIM];    // St[c_out][n] (K-major)

// ---------------- helpers ----------------
__device__ __forceinline__ uint32_t smem_u32(const void* p) {
    uint32_t a;
    asm("{ .reg .u64 t; cvta.to.shared.u64 t, %1; cvt.u32.u64 %0, t; }" : "=r"(a) : "l"(p));
    return a;
}

__device__ __forceinline__ void cp_async16(uint32_t dst, const void* src) {
    asm volatile("cp.async.cg.shared.global [%0], [%1], 16;\n"
                 :: "r"(dst), "l"(__cvta_generic_to_global(src)) : "memory");
}
#define CP_COMMIT()  asm volatile("cp.async.commit_group;\n" ::: "memory")
#define CP_WAIT2()   asm volatile("cp.async.wait_group 2;\n" ::: "memory")

__device__ __forceinline__ void ldm_x4(uint32_t* r, uint32_t addr) {
    asm volatile("ldmatrix.sync.aligned.m8n8.x4.shared.b16 {%0,%1,%2,%3}, [%4];\n"
                 : "=r"(r[0]), "=r"(r[1]), "=r"(r[2]), "=r"(r[3]) : "r"(addr));
}

__device__ __forceinline__ void mma_16816(float* c, const uint32_t* a, const uint32_t* b) {
    asm volatile(
        "mma.sync.aligned.m16n8k16.row.col.f32.f16.f16.f32 "
        "{%0,%1,%2,%3}, {%4,%5,%6,%7}, {%8,%9}, {%0,%1,%2,%3};\n"
        : "+f"(c[0]), "+f"(c[1]), "+f"(c[2]), "+f"(c[3])
        : "r"(a[0]), "r"(a[1]), "r"(a[2]), "r"(a[3]), "r"(b[0]), "r"(b[1]));
}

// ============================================================
// Kernel 1: fp16 transposed sine basis.
// g_S[c][n] = sin(pi*(2n+1)*(c+1)/2048), exact integer angle reduction.
// ============================================================
__global__ void build_basis_kernel() {
    int c = blockIdx.x;  // output index
    for (int n = threadIdx.x; n < NDIM; n += blockDim.x) {
        int m = ((2 * n + 1) * (c + 1)) & 4095;   // sin period 4096
        float s = sinpif((float)m * (1.0f / 2048.0f));
        g_S[(size_t)c * NDIM + n] = __float2half_rn(s);
    }
}

// ============================================================
// Kernel 2: x fp32 -> fp16
// ============================================================
__global__ void convert_x_kernel(const float* __restrict__ x) {
    size_t i = (size_t)blockIdx.x * blockDim.x + threadIdx.x;  // float4 idx
    float4 v = reinterpret_cast<const float4*>(x)[i];
    __half2 h0 = __floats2half2_rn(v.x, v.y);
    __half2 h1 = __floats2half2_rn(v.z, v.w);
    uint2 o;
    o.x = *reinterpret_cast<uint32_t*>(&h0);
    o.y = *reinterpret_cast<uint32_t*>(&h1);
    reinterpret_cast<uint2*>(g_x)[i] = o;
}

// ============================================================
// Kernel 3: pipelined fp16 mma.sync GEMM.
// CTA 128x128, K-chunk 64, 4-stage cp.async ring, 8 warps (2m x 4n),
// warp tile 64x32 = 4 m16 x 4 n8 fragments.
// ============================================================
__global__ void __launch_bounds__(256, 1)
dst_gemm_kernel(float* __restrict__ y) {
    extern __shared__ char smem[];
    const uint32_t sb = smem_u32(smem);
    const int tid  = threadIdx.x;
    const int wid  = tid >> 5;
    const int lane = tid & 31;

    const int m_base = (blockIdx.x >> 3) * TILE_M;
    const int n_base = (blockIdx.x & 7) * TILE_N;
    const int wm = (wid & 1) * 64;   // warp m offset in tile
    const int wn = (wid >> 1) * 32;  // warp n offset in tile

    float acc[4][4][4];
    #pragma unroll
    for (int i = 0; i < 4; i++)
        #pragma unroll
        for (int j = 0; j < 4; j++)
            #pragma unroll
            for (int q = 0; q < 4; q++) acc[i][j][q] = 0.0f;

    // ---- loader: chunk kc -> stage kc&3 ----
    auto issue = [&](int kc) {
        uint32_t st = sb + (uint32_t)(kc & 3) * STAGE_BYTES;
        int kb = kc * KB;
        #pragma unroll
        for (int i = 0; i < 4; i++) {
            int idx = i * 256 + tid;          // 0..1023
            int r = idx >> 3;                 // row 0..127
            int c = idx & 7;                  // 16B chunk 0..7
            uint32_t sw = (uint32_t)((c ^ (r & 7)) << 4);
            cp_async16(st + r * 128 + sw,
                       g_x + (size_t)(m_base + r) * NDIM + kb + c * 8);
            cp_async16(st + STAGE_A + r * 128 + sw,
                       g_S + (size_t)(n_base + r) * NDIM + kb + c * 8);
        }
        CP_COMMIT();
    };

    issue(0); issue(1); issue(2);

    const int j  = lane >> 3;   // matrix index within ldmatrix.x4
    const int ri = lane & 7;    // row within matrix

    for (int kc = 0; kc < NCHUNK; kc++) {
        CP_WAIT2();             // chunk kc resident
        __syncthreads();
        if (kc + 3 < NCHUNK) issue(kc + 3);
        else CP_COMMIT();       // keep group count invariant

        uint32_t st = sb + (uint32_t)(kc & 3) * STAGE_BYTES;

        #pragma unroll
        for (int ks = 0; ks < 4; ks++) {            // k16 steps in chunk
            uint32_t a[4][4], b[4][2];
            // A fragments: 4 x m16k16
            #pragma unroll
            for (int mi = 0; mi < 4; mi++) {
                int row = wm + mi * 16 + ((j & 1) << 3) + ri;
                int c   = ks * 2 + (j >> 1);
                ldm_x4(a[mi], st + row * 128 + (uint32_t)((c ^ (row & 7)) << 4));
            }
            // B fragments: 2 x (two n8k16 each)
            #pragma unroll
            for (int nh = 0; nh < 2; nh++) {
                int row = wn + nh * 16 + ((j >> 1) << 3) + ri;
                int c   = ks * 2 + (j & 1);
                uint32_t t[4];
                ldm_x4(t, st + STAGE_A + row * 128 + (uint32_t)((c ^ (row & 7)) << 4));
                b[2 * nh + 0][0] = t[0]; b[2 * nh + 0][1] = t[1];
                b[2 * nh + 1][0] = t[2]; b[2 * nh + 1][1] = t[3];
            }
            #pragma unroll
            for (int mi = 0; mi < 4; mi++)
                #pragma unroll
                for (int nj = 0; nj < 4; nj++)
                    mma_16816(acc[mi][nj], a[mi], b[nj]);
        }
    }

    // ---- epilogue: direct vectorized stores ----
    const int r_lane = lane >> 2;
    const int c_lane = (lane & 3) * 2;
    #pragma unroll
    for (int mi = 0; mi < 4; mi++) {
        int r0 = m_base + wm + mi * 16 + r_lane;
        #pragma unroll
        for (int nj = 0; nj < 4; nj++) {
            int c0 = n_base + wn + nj * 8 + c_lane;
            float2 v0 = make_float2(acc[mi][nj][0], acc[mi][nj][1]);
            float2 v1 = make_float2(acc[mi][nj][2], acc[mi][nj][3]);
            *reinterpret_cast<float2*>(y + (size_t)r0 * NDIM + c0) = v0;
            *reinterpret_cast<float2*>(y + (size_t)(r0 + 8) * NDIM + c0) = v1;
        }
    }
}

// ============================================================
// Launch
// ============================================================
extern "C" void kernel_launch(void* const* d_in, const int* in_sizes, int n_in,
                              void* d_out, int out_size) {
    const float* x = (const float*)d_in[0];
    float* y = (float*)d_out;

    build_basis_kernel<<<NDIM, 256>>>();
    convert_x_kernel<<<(BATCH * NDIM / 4) / 256, 256>>>(x);

    cudaFuncSetAttribute(dst_gemm_kernel,
                         cudaFuncAttributeMaxDynamicSharedMemorySize, SMEM_TOTAL);
    int grid = (BATCH / TILE_M) * (NDIM / TILE_N);  // 1024
    dst_gemm_kernel<<<grid, 256, SMEM_TOTAL>>>(y);
}

// round 3
// speedup vs baseline: 1.3257x; 1.3257x over previous
#include <cuda_runtime.h>
#include <cuda_fp16.h>
#include <cstdint>

// ============================================================
// DST-II via reflection fold:
//   u_n = x_n + x_{1023-n}, v_n = x_n - x_{1023-n}   (n < 512)
//   y_{2j}   = sum_n u_n * sin(pi/1024 (n+.5)(2j+1))
//   y_{2j+1} = sum_n v_n * sin(pi/1024 (n+.5)(2j+2))
// => two [16384,512]x[512,512] fp16 GEMMs fused in one kernel.
// ============================================================

#define BATCH   16384
#define NDIM    1024
#define KDIM    512
#define TILE_M  128
#define TILE_J  64            // j values per CTA -> 128 output cols
#define KB      64            // K per chunk (128B rows)
#define NCHUNK  (KDIM / KB)   // 8
#define NSTAGE  3

// stage layout (bytes)
#define OFF_U   0             // 128 x 64 fp16 = 16384
#define OFF_V   16384
#define OFF_SE  32768         // 64 x 64 fp16 = 8192
#define OFF_SO  40960
#define STAGE_BYTES 49152
#define SMEM_TOTAL  (NSTAGE * STAGE_BYTES)   // 147456
#define EPI_PITCH   132       // floats per row in epilogue staging

// ---------------- device scratch ----------------
__device__ __half g_u[(size_t)BATCH * KDIM];
__device__ __half g_v[(size_t)BATCH * KDIM];
__device__ __half g_Se[(size_t)KDIM * KDIM];   // [j][n], n contiguous
__device__ __half g_So[(size_t)KDIM * KDIM];

// ---------------- helpers ----------------
__device__ __forceinline__ uint32_t smem_u32(const void* p) {
    uint32_t a;
    asm("{ .reg .u64 t; cvta.to.shared.u64 t, %1; cvt.u32.u64 %0, t; }" : "=r"(a) : "l"(p));
    return a;
}
__device__ __forceinline__ void cp_async16(uint32_t dst, const void* src) {
    asm volatile("cp.async.cg.shared.global [%0], [%1], 16;\n"
                 :: "r"(dst), "l"(__cvta_generic_to_global(src)) : "memory");
}
#define CP_COMMIT()  asm volatile("cp.async.commit_group;\n" ::: "memory")
#define CP_WAIT1()   asm volatile("cp.async.wait_group 1;\n" ::: "memory")

__device__ __forceinline__ void ldm_x4(uint32_t* r, uint32_t addr) {
    asm volatile("ldmatrix.sync.aligned.m8n8.x4.shared.b16 {%0,%1,%2,%3}, [%4];\n"
                 : "=r"(r[0]), "=r"(r[1]), "=r"(r[2]), "=r"(r[3]) : "r"(addr));
}
__device__ __forceinline__ void mma_16816(float* c, const uint32_t* a, const uint32_t* b) {
    asm volatile(
        "mma.sync.aligned.m16n8k16.row.col.f32.f16.f16.f32 "
        "{%0,%1,%2,%3}, {%4,%5,%6,%7}, {%8,%9}, {%0,%1,%2,%3};\n"
        : "+f"(c[0]), "+f"(c[1]), "+f"(c[2]), "+f"(c[3])
        : "r"(a[0]), "r"(a[1]), "r"(a[2]), "r"(a[3]), "r"(b[0]), "r"(b[1]));
}

// ============================================================
// Kernel 1: folded sine bases (exact integer angle reduction).
// ============================================================
__global__ void build_basis_kernel() {
    int j = blockIdx.x;  // 0..511
    for (int n = threadIdx.x; n < KDIM; n += blockDim.x) {
        int me = ((2 * n + 1) * (2 * j + 1)) & 4095;
        int mo = ((2 * n + 1) * (2 * j + 2)) & 4095;
        g_Se[(size_t)j * KDIM + n] = __float2half_rn(sinpif((float)me * (1.0f / 2048.0f)));
        g_So[(size_t)j * KDIM + n] = __float2half_rn(sinpif((float)mo * (1.0f / 2048.0f)));
    }
}

// ============================================================
// Kernel 2: fold x -> u, v (fp16)
// ============================================================
__global__ void fold_x_kernel(const float* __restrict__ x) {
    size_t i = (size_t)blockIdx.x * blockDim.x + threadIdx.x;  // one float4 of u/v
    size_t b  = i >> 7;          // row
    int    c4 = (int)(i & 127);  // float4 index within 512 cols
    int    c  = c4 * 4;
    const float* row = x + b * NDIM;
    float4 f = *reinterpret_cast<const float4*>(row + c);
    float4 rr = *reinterpret_cast<const float4*>(row + (1020 - c));  // cols 1020-c .. 1023-c
    // reversed: partner of col c+t is col 1023-(c+t) = (1020-c) + (3-t)
    float4 r4 = make_float4(rr.w, rr.z, rr.y, rr.x);
    __half2 u0 = __floats2half2_rn(f.x + r4.x, f.y + r4.y);
    __half2 u1 = __floats2half2_rn(f.z + r4.z, f.w + r4.w);
    __half2 v0 = __floats2half2_rn(f.x - r4.x, f.y - r4.y);
    __half2 v1 = __floats2half2_rn(f.z - r4.z, f.w - r4.w);
    uint2 uu, vv;
    uu.x = *reinterpret_cast<uint32_t*>(&u0); uu.y = *reinterpret_cast<uint32_t*>(&u1);
    vv.x = *reinterpret_cast<uint32_t*>(&v0); vv.y = *reinterpret_cast<uint32_t*>(&v1);
    reinterpret_cast<uint2*>(g_u)[b * 128 + c4] = uu;
    reinterpret_cast<uint2*>(g_v)[b * 128 + c4] = vv;
}

// ============================================================
// Kernel 3: fused dual-parity GEMM.
// 8 warps: bit0 = parity (u/Se vs v/So), bit1 = j-half, bit2 = m-half.
// Warp tile 64x32 (4 m16 x 4 n8), K=512, 3-stage cp.async pipeline.
// Epilogue interleaves parities through padded smem, coalesced stores.
// ============================================================
__global__ void __launch_bounds__(256, 1)
dst_gemm_kernel(float* __restrict__ y) {
    extern __shared__ char smem[];
    const uint32_t sb = smem_u32(smem);
    const int tid  = threadIdx.x;
    const int wid  = tid >> 5;
    const int lane = tid & 31;

    const int m_base = (blockIdx.x >> 3) * TILE_M;
    const int jt     = blockIdx.x & 7;          // j-tile
    const int j_base = jt * TILE_J;

    const int par = wid & 1;                    // 0: even outputs, 1: odd
    const int wn  = ((wid >> 1) & 1) * 32;      // j offset within tile
    const int wm  = ((wid >> 2) & 1) * 64;      // m offset within tile
    const uint32_t aoff = par ? OFF_V : OFF_U;
    const uint32_t boff = par ? OFF_SO : OFF_SE;

    float acc[4][4][4];
    #pragma unroll
    for (int i = 0; i < 4; i++)
        #pragma unroll
        for (int j = 0; j < 4; j++)
            #pragma unroll
            for (int q = 0; q < 4; q++) acc[i][j][q] = 0.0f;

    auto issue = [&](int kc) {
        uint32_t st = sb + (uint32_t)(kc % NSTAGE) * STAGE_BYTES;
        int kb = kc * KB;
        // U, V: 128 rows x 64 cols
        #pragma unroll
        for (int i = 0; i < 4; i++) {
            int idx = i * 256 + tid;
            int r = idx >> 3, c = idx & 7;
            uint32_t sw = (uint32_t)((c ^ (r & 7)) << 4);
            size_t g = (size_t)(m_base + r) * KDIM + kb + c * 8;
            cp_async16(st + OFF_U + r * 128 + sw, g_u + g);
            cp_async16(st + OFF_V + r * 128 + sw, g_v + g);
        }
        // Se, So: 64 rows x 64 cols
        #pragma unroll
        for (int i = 0; i < 2; i++) {
            int idx = i * 256 + tid;
            int r = idx >> 3, c = idx & 7;
            uint32_t sw = (uint32_t)((c ^ (r & 7)) << 4);
            size_t g = (size_t)(j_base + r) * KDIM + kb + c * 8;
            cp_async16(st + OFF_SE + r * 128 + sw, g_Se + g);
            cp_async16(st + OFF_SO + r * 128 + sw, g_So + g);
        }
        CP_COMMIT();
    };

    issue(0); issue(1);

    const int jj = lane >> 3;   // ldmatrix sub-matrix selector
    const int ri = lane & 7;

    for (int kc = 0; kc < NCHUNK; kc++) {
        CP_WAIT1();
        __syncthreads();
        if (kc + 2 < NCHUNK) issue(kc + 2);
        else CP_COMMIT();

        uint32_t st = sb + (uint32_t)(kc % NSTAGE) * STAGE_BYTES;
        uint32_t abase = st + aoff;
        uint32_t bbase = st + boff;

        #pragma unroll
        for (int ks = 0; ks < 4; ks++) {
            uint32_t a[4][4], b[4][2];
            #pragma unroll
            for (int mi = 0; mi < 4; mi++) {
                int row = wm + mi * 16 + ((jj & 1) << 3) + ri;
                int c   = ks * 2 + (jj >> 1);
                ldm_x4(a[mi], abase + row * 128 + (uint32_t)((c ^ (row & 7)) << 4));
            }
            #pragma unroll
            for (int nh = 0; nh < 2; nh++) {
                int row = wn + nh * 16 + ((jj >> 1) << 3) + ri;
                int c   = ks * 2 + (jj & 1);
                uint32_t t[4];
                ldm_x4(t, bbase + row * 128 + (uint32_t)((c ^ (row & 7)) << 4));
                b[2 * nh + 0][0] = t[0]; b[2 * nh + 0][1] = t[1];
                b[2 * nh + 1][0] = t[2]; b[2 * nh + 1][1] = t[3];
            }
            #pragma unroll
            for (int mi = 0; mi < 4; mi++)
                #pragma unroll
                for (int nj = 0; nj < 4; nj++)
                    mma_16816(acc[mi][nj], a[mi], b[nj]);
        }
    }

    // ---- epilogue: interleave parities via padded smem, coalesced stores ----
    __syncthreads();   // done reading pipeline buffers
    float* sf = reinterpret_cast<float*>(smem);
    const int r_lane = lane >> 2;
    const int c_lane = (lane & 3) * 2;
    #pragma unroll
    for (int mi = 0; mi < 4; mi++) {
        int r0 = wm + mi * 16 + r_lane;
        #pragma unroll
        for (int nj = 0; nj < 4; nj++) {
            int gc = 2 * (wn + nj * 8 + c_lane) + par;   // interleaved col in [0,128)
            sf[(size_t)r0 * EPI_PITCH + gc]           = acc[mi][nj][0];
            sf[(size_t)r0 * EPI_PITCH + gc + 2]       = acc[mi][nj][1];
            sf[(size_t)(r0 + 8) * EPI_PITCH + gc]     = acc[mi][nj][2];
            sf[(size_t)(r0 + 8) * EPI_PITCH + gc + 2] = acc[mi][nj][3];
        }
    }
    __syncthreads();
    #pragma unroll
    for (int i = 0; i < 16; i++) {
        int lin = i * 256 + tid;        // 4096 float4s
        int r = lin >> 5, c4 = lin & 31;
        float4 v = *reinterpret_cast<float4*>(sf + (size_t)r * EPI_PITCH + c4 * 4);
        *reinterpret_cast<float4*>(y + (size_t)(m_base + r) * NDIM + jt * 128 + c4 * 4) = v;
    }
}

// ============================================================
// Launch
// ============================================================
extern "C" void kernel_launch(void* const* d_in, const int* in_sizes, int n_in,
                              void* d_out, int out_size) {
    const float* x = (const float*)d_in[0];
    float* y = (float*)d_out;

    build_basis_kernel<<<KDIM, 256>>>();
    fold_x_kernel<<<(int)(((size_t)BATCH * 128) / 256), 256>>>(x);

    cudaFuncSetAttribute(dst_gemm_kernel,
                         cudaFuncAttributeMaxDynamicSharedMemorySize, SMEM_TOTAL);
    int grid = (BATCH / TILE_M) * (NDIM / (2 * TILE_J));  // 128 * 8 = 1024
    dst_gemm_kernel<<<grid, 256, SMEM_TOTAL>>>(y);
}